// round 1
// baseline (speedup 1.0000x reference)
#include <cuda_runtime.h>

#define Bq   32
#define Nn   512
#define Tt   (Bq*Nn)          // 16384 tokens
#define Fd   1024
#define Md   256
#define Ee   8
#define TT   128              // token tile
#define CT   128              // column tile
#define KT   16               // k tile
#define NTILES (Tt/TT + Ee)   // 136 max padded tiles
#define SORT_SZ (Tt + Ee*TT)  // 17408
#define OUTD 17
#define EPSV 1e-8f

// scratch (device globals: allocation-free)
__device__ int   g_cnt[Ee];
__device__ int   g_fill[Ee];
__device__ int   g_off[Ee+1];
__device__ int   g_sorted[SORT_SZ];
__device__ float g_h1[(size_t)SORT_SZ*Md];
__device__ float g_r1[(size_t)SORT_SZ*Md];

__global__ void k_init() {
    int i = blockIdx.x*256 + threadIdx.x;
    if (i < Ee) { g_cnt[i] = 0; g_fill[i] = 0; }
    if (i < SORT_SZ) g_sorted[i] = -1;
}

__global__ void k_count(const int* __restrict__ sem) {
    int t = blockIdx.x*256 + threadIdx.x;
    if (t < Tt) atomicAdd(&g_cnt[sem[t]], 1);
}

__global__ void k_offsets() {
    if (threadIdx.x == 0) {
        int acc = 0;
        for (int e = 0; e < Ee; e++) {
            g_off[e] = acc;
            acc += ((g_cnt[e] + TT - 1) / TT) * TT;
        }
        g_off[Ee] = acc;
    }
}

__global__ void k_scatter(const int* __restrict__ sem) {
    int t = blockIdx.x*256 + threadIdx.x;
    if (t < Tt) {
        int e = sem[t];
        int pos = g_off[e] + atomicAdd(&g_fill[e], 1);
        g_sorted[pos] = t;
    }
}

// Layer 1: for sorted tokens, h1 = relu(x@W1[e]+b1[e]) and r1 = relu(x@R1[e]+rb1[e])
// Grid: (NTILES, 4). blockIdx.y in {0,1}: W1 cols; {2,3}: R1 cols.
__global__ void __launch_bounds__(256, 2)
k_gemm1(const float* __restrict__ nodes,
        const float* __restrict__ W1, const float* __restrict__ b1,
        const float* __restrict__ R1, const float* __restrict__ rb1)
{
    __shared__ float Xs[2][KT][TT];
    __shared__ float Ws[2][KT][CT];
    __shared__ int soff[Ee+1];

    int tid = threadIdx.x;
    if (tid < Ee+1) soff[tid] = g_off[tid];
    __syncthreads();

    int p0 = blockIdx.x * TT;
    if (p0 >= soff[Ee]) return;          // block-uniform
    int e = 0;
    while (e < Ee-1 && p0 >= soff[e+1]) e++;

    int cGlob = blockIdx.y * CT;
    const float* Wp; const float* bp; float* dst; int cm0;
    if (cGlob < Md) { Wp = W1 + (size_t)e*Fd*Md; bp = b1 + e*Md;  dst = g_h1; cm0 = cGlob; }
    else            { Wp = R1 + (size_t)e*Fd*Md; bp = rb1 + e*Md; dst = g_r1; cm0 = cGlob - Md; }

    // X-load mapping: 2 threads per token row, 8 consecutive k each
    int xi  = tid >> 1;
    int xk0 = (tid & 1) * 8;
    int t_xi = g_sorted[p0 + xi];
    bool xvalid = (t_xi >= 0);
    const float* xrow = nodes + (size_t)(xvalid ? t_xi : 0) * Fd;

    // W-load mapping: 128 threads across columns, 8 k-rows each
    int wc  = tid & 127;
    int wk0 = tid >> 7;

    float acc[8][8];
    #pragma unroll
    for (int i = 0; i < 8; i++)
        #pragma unroll
        for (int j = 0; j < 8; j++) acc[i][j] = 0.f;

    int rr = (tid >> 4) * 8;   // token-row base of micro tile
    int cc = (tid & 15) * 8;   // col base of micro tile

    auto loadstage = [&](int buf, int k0) {
        float4 v0, v1;
        if (xvalid) {
            v0 = *reinterpret_cast<const float4*>(xrow + k0 + xk0);
            v1 = *reinterpret_cast<const float4*>(xrow + k0 + xk0 + 4);
        } else {
            v0 = make_float4(0.f,0.f,0.f,0.f); v1 = v0;
        }
        Xs[buf][xk0+0][xi] = v0.x; Xs[buf][xk0+1][xi] = v0.y;
        Xs[buf][xk0+2][xi] = v0.z; Xs[buf][xk0+3][xi] = v0.w;
        Xs[buf][xk0+4][xi] = v1.x; Xs[buf][xk0+5][xi] = v1.y;
        Xs[buf][xk0+6][xi] = v1.z; Xs[buf][xk0+7][xi] = v1.w;
        const float* wbase = Wp + (size_t)k0*Md + cm0 + wc;
        #pragma unroll
        for (int s = 0; s < 8; s++)
            Ws[buf][wk0 + 2*s][wc] = wbase[(size_t)(wk0 + 2*s)*Md];
    };

    loadstage(0, 0);
    int buf = 0;
    for (int k0 = 0; k0 < Fd; k0 += KT) {
        __syncthreads();
        if (k0 + KT < Fd) loadstage(buf ^ 1, k0 + KT);
        #pragma unroll
        for (int kk = 0; kk < KT; kk++) {
            float4 x0 = *reinterpret_cast<const float4*>(&Xs[buf][kk][rr]);
            float4 x1 = *reinterpret_cast<const float4*>(&Xs[buf][kk][rr+4]);
            float4 w0 = *reinterpret_cast<const float4*>(&Ws[buf][kk][cc]);
            float4 w1 = *reinterpret_cast<const float4*>(&Ws[buf][kk][cc+4]);
            float xr[8] = {x0.x,x0.y,x0.z,x0.w,x1.x,x1.y,x1.z,x1.w};
            float wr[8] = {w0.x,w0.y,w0.z,w0.w,w1.x,w1.y,w1.z,w1.w};
            #pragma unroll
            for (int i = 0; i < 8; i++)
                #pragma unroll
                for (int j = 0; j < 8; j++)
                    acc[i][j] += xr[i] * wr[j];
        }
        buf ^= 1;
    }

    // epilogue: bias + relu + store
    #pragma unroll
    for (int i = 0; i < 8; i++) {
        int p = p0 + rr + i;
        float* drow = dst + (size_t)p*Md + cm0 + cc;
        float4 o0, o1;
        o0.x = fmaxf(acc[i][0] + bp[cm0+cc+0], 0.f);
        o0.y = fmaxf(acc[i][1] + bp[cm0+cc+1], 0.f);
        o0.z = fmaxf(acc[i][2] + bp[cm0+cc+2], 0.f);
        o0.w = fmaxf(acc[i][3] + bp[cm0+cc+3], 0.f);
        o1.x = fmaxf(acc[i][4] + bp[cm0+cc+4], 0.f);
        o1.y = fmaxf(acc[i][5] + bp[cm0+cc+5], 0.f);
        o1.z = fmaxf(acc[i][6] + bp[cm0+cc+6], 0.f);
        o1.w = fmaxf(acc[i][7] + bp[cm0+cc+7], 0.f);
        *reinterpret_cast<float4*>(drow)     = o0;
        *reinterpret_cast<float4*>(drow + 4) = o1;
    }
}

// Tail: layers 2-4 + rot2 + masked write. One block per token tile.
__global__ void __launch_bounds__(256, 2)
k_tail(const float* __restrict__ W2, const float* __restrict__ b2,
       const float* __restrict__ W3, const float* __restrict__ b3,
       const float* __restrict__ W4, const float* __restrict__ b4,
       const float* __restrict__ R2, const float* __restrict__ rb2,
       const int* __restrict__ lengths, float* __restrict__ out)
{
    extern __shared__ float sm[];
    float* sW2  = sm;               // 256*64
    float* sW3  = sW2 + Md*64;      // 64*32
    float* sW4  = sW3 + 64*32;      // 32*14
    float* sR2  = sW4 + 32*14;      // 256*3
    float* sb2  = sR2 + Md*3;       // 64
    float* sb3  = sb2 + 64;         // 32
    float* sb4  = sb3 + 32;         // 14
    float* srb2 = sb4 + 14;         // 3
    float* sh1  = srb2 + 3;         // 8*256
    float* sr1  = sh1 + 8*Md;       // 8*256
    float* sh2  = sr1 + 8*Md;       // 8*64
    float* sh3  = sh2 + 8*64;       // 8*32

    __shared__ int soff[Ee+1];
    int tid = threadIdx.x;
    if (tid < Ee+1) soff[tid] = g_off[tid];
    __syncthreads();

    int p0 = blockIdx.x * TT;
    if (p0 >= soff[Ee]) return;
    int e = 0;
    while (e < Ee-1 && p0 >= soff[e+1]) e++;

    // stage weights
    const float* gW2 = W2 + (size_t)e*Md*64;
    for (int i = tid; i < Md*64; i += 256) sW2[i] = gW2[i];
    const float* gW3 = W3 + e*64*32;
    for (int i = tid; i < 64*32; i += 256) sW3[i] = gW3[i];
    const float* gW4 = W4 + e*32*14;
    for (int i = tid; i < 32*14; i += 256) sW4[i] = gW4[i];
    const float* gR2 = R2 + e*Md*3;
    for (int i = tid; i < Md*3; i += 256) sR2[i] = gR2[i];
    if (tid < 64) sb2[tid]  = b2[e*64 + tid];
    if (tid < 32) sb3[tid]  = b3[e*32 + tid];
    if (tid < 14) sb4[tid]  = b4[e*14 + tid];
    if (tid < 3)  srb2[tid] = rb2[e*3 + tid];
    __syncthreads();

    int w = tid >> 5, lane = tid & 31;
    float* h1w = sh1 + w*Md;
    float* r1w = sr1 + w*Md;
    float* h2w = sh2 + w*64;
    float* h3w = sh3 + w*32;

    for (int it = 0; it < 16; it++) {
        int p = p0 + w*16 + it;
        int t = g_sorted[p];
        if (t < 0) continue;                      // warp-uniform

        #pragma unroll
        for (int u = 0; u < 8; u++) {
            h1w[lane + 32*u] = g_h1[(size_t)p*Md + lane + 32*u];
            r1w[lane + 32*u] = g_r1[(size_t)p*Md + lane + 32*u];
        }
        __syncwarp();

        // layer 2: 256 -> 64 (2 outputs per lane, float2 weight reads)
        int j0 = 2*lane;
        float a0 = sb2[j0], a1 = sb2[j0+1];
        #pragma unroll 4
        for (int m = 0; m < Md; m++) {
            float hv = h1w[m];
            float2 wv = *reinterpret_cast<const float2*>(&sW2[m*64 + j0]);
            a0 += hv * wv.x; a1 += hv * wv.y;
        }
        h2w[j0]   = fmaxf(a0, 0.f);
        h2w[j0+1] = fmaxf(a1, 0.f);
        __syncwarp();

        // layer 3: 64 -> 32
        float a = sb3[lane];
        #pragma unroll
        for (int h = 0; h < 64; h++) a += h2w[h] * sW3[h*32 + lane];
        h3w[lane] = fmaxf(a, 0.f);
        __syncwarp();

        // layer 4: 32 -> 14
        float y = 0.f;
        if (lane < 14) {
            y = sb4[lane];
            #pragma unroll
            for (int g = 0; g < 32; g++) y += h3w[g] * sW4[g*14 + lane];
        }

        // rot: 256 -> 3, warp reduction
        float r0 = 0.f, r1v = 0.f, r2 = 0.f;
        #pragma unroll
        for (int u = 0; u < 8; u++) {
            int m = lane + 32*u;
            float rv = r1w[m];
            r0  += rv * sR2[m*3 + 0];
            r1v += rv * sR2[m*3 + 1];
            r2  += rv * sR2[m*3 + 2];
        }
        #pragma unroll
        for (int s = 16; s > 0; s >>= 1) {
            r0  += __shfl_xor_sync(0xffffffff, r0, s);
            r1v += __shfl_xor_sync(0xffffffff, r1v, s);
            r2  += __shfl_xor_sync(0xffffffff, r2, s);
        }

        int b = t >> 9, n = t & (Nn - 1);
        bool masked = (n >= lengths[b]);
        float* op = out + (size_t)t*OUTD;
        if (masked) {
            if (lane < OUTD) op[lane] = EPSV;
        } else {
            if (lane < 14) op[lane] = y;
            if (lane == 0) {
                op[14] = r0  + srb2[0];
                op[15] = r1v + srb2[1];
                op[16] = r2  + srb2[2];
            }
        }
    }
}

static const int TAIL_SMEM_BYTES =
    (Md*64 + 64*32 + 32*14 + Md*3 + 64 + 32 + 14 + 3 + 8*Md + 8*Md + 8*64 + 8*32) * 4;

extern "C" void kernel_launch(void* const* d_in, const int* in_sizes, int n_in,
                              void* d_out, int out_size) {
    const float* nodes   = (const float*)d_in[0];
    const int*   sem     = (const int*)  d_in[1];
    const int*   lengths = (const int*)  d_in[2];
    const float* W1 = (const float*)d_in[3];  const float* b1  = (const float*)d_in[4];
    const float* W2 = (const float*)d_in[5];  const float* b2  = (const float*)d_in[6];
    const float* W3 = (const float*)d_in[7];  const float* b3  = (const float*)d_in[8];
    const float* W4 = (const float*)d_in[9];  const float* b4  = (const float*)d_in[10];
    const float* R1 = (const float*)d_in[11]; const float* rb1 = (const float*)d_in[12];
    const float* R2 = (const float*)d_in[13]; const float* rb2 = (const float*)d_in[14];
    float* out = (float*)d_out;

    cudaFuncSetAttribute(k_tail, cudaFuncAttributeMaxDynamicSharedMemorySize, TAIL_SMEM_BYTES);

    k_init   <<<(SORT_SZ + 255)/256, 256>>>();
    k_count  <<<Tt/256, 256>>>(sem);
    k_offsets<<<1, 32>>>();
    k_scatter<<<Tt/256, 256>>>(sem);
    dim3 g1(NTILES, 4);
    k_gemm1  <<<g1, 256>>>(nodes, W1, b1, R1, rb1);
    k_tail   <<<NTILES, 256, TAIL_SMEM_BYTES>>>(W2, b2, W3, b3, W4, b4, R2, rb2, lengths, out);
}

// round 6
// speedup vs baseline: 1.8286x; 1.8286x over previous
#include <cuda_runtime.h>
#include <cstdint>

#define Bq   32
#define Nn   512
#define Tt   (Bq*Nn)          // 16384 tokens
#define Fd   1024
#define Md   256
#define Ee   8
#define TT   128              // token tile
#define NTILES (Tt/TT + Ee)   // 136 max padded tiles
#define SORT_SZ (Tt + Ee*TT)  // 17408
#define OUTD 17
#define EPSV 1e-8f

// GEMM tiling
#define KC 32
#define KSTEPS (Fd/KC)        // 32
#define XPITCH 36             // 32 + 4 pad (floats)
#define WPITCH 136            // 128 + 8 pad
#define EPITCH 132            // 128 + 4 pad
#define SF (TT*XPITCH + KC*WPITCH)     // stage floats = 4608 + 4352 = 8960
#define GEMM_SMEM ((2*SF + 128) * 4)   // 72192 bytes

// ---------------- device scratch ----------------
__device__ int   g_cnt[Ee];
__device__ int   g_fill[Ee];
__device__ int   g_off[Ee+1];
__device__ int   g_sorted[SORT_SZ];
__device__ float g_h1[(size_t)SORT_SZ*Md];
__device__ float g_r1[(size_t)SORT_SZ*Md];

// ---------------- helpers ----------------
__device__ __forceinline__ uint32_t s2u(const void* p) {
    return (uint32_t)__cvta_generic_to_shared((void*)p);
}
__device__ __forceinline__ uint32_t f2tf(float x) {
    uint32_t r;
    asm("cvt.rna.tf32.f32 %0, %1;" : "=r"(r) : "f"(x));
    return r;
}
__device__ __forceinline__ void cpa16(uint32_t d, const void* s) {
    asm volatile("cp.async.cg.shared.global [%0], [%1], 16;" :: "r"(d), "l"(s));
}
__device__ __forceinline__ void cpa16z(uint32_t d, const void* s, uint32_t sz) {
    asm volatile("cp.async.cg.shared.global [%0], [%1], 16, %2;" :: "r"(d), "l"(s), "r"(sz));
}

// ---------------- sort prep ----------------
__global__ void k_init() {
    int i = blockIdx.x*256 + threadIdx.x;
    if (i < Ee) { g_cnt[i] = 0; g_fill[i] = 0; }
    if (i < SORT_SZ) g_sorted[i] = -1;
}
__global__ void k_count(const int* __restrict__ sem) {
    int t = blockIdx.x*256 + threadIdx.x;
    if (t < Tt) atomicAdd(&g_cnt[sem[t]], 1);
}
__global__ void k_offsets() {
    if (threadIdx.x == 0) {
        int acc = 0;
        for (int e = 0; e < Ee; e++) {
            g_off[e] = acc;
            acc += ((g_cnt[e] + TT - 1) / TT) * TT;
        }
        g_off[Ee] = acc;
    }
}
__global__ void k_scatter(const int* __restrict__ sem) {
    int t = blockIdx.x*256 + threadIdx.x;
    if (t < Tt) {
        int e = sem[t];
        int pos = g_off[e] + atomicAdd(&g_fill[e], 1);
        g_sorted[pos] = t;
    }
}

// ---------------- layer-1 GEMM on mma.sync tf32 ----------------
// grid (NTILES, 4): y>>1 = branch (0:W1->g_h1, 1:R1->g_r1), y&1 = column half.
// CTA computes [128 cols (M)] x [128 tokens (N)], K=1024.
__global__ void __launch_bounds__(256, 2)
k_gemm1_mma(const float* __restrict__ nodes,
            const float* __restrict__ W1, const float* __restrict__ b1,
            const float* __restrict__ R1, const float* __restrict__ rb1)
{
    extern __shared__ float sm[];
    __shared__ int soff[Ee+1];

    int tid = threadIdx.x;
    if (tid < Ee+1) soff[tid] = g_off[tid];
    __syncthreads();

    int p0 = blockIdx.x * TT;
    if (p0 >= soff[Ee]) return;
    int e = 0;
    while (e < Ee-1 && p0 >= soff[e+1]) e++;

    bool rotb = (blockIdx.y >= 2);
    int  half = blockIdx.y & 1;
    const float* Wsrc = (rotb ? R1 : W1) + (size_t)e*Fd*Md + half*128;
    const float* bias = (rotb ? rb1 : b1) + e*Md + half*128;
    float*       dst  = rotb ? g_r1 : g_h1;

    float* sbias = sm + 2*SF;
    for (int i = tid; i < 128; i += 256) sbias[i] = bias[i];

    // per-thread cp.async source setup
    // X: 2 threads per token row, 4x16B each (128B per row per stage)
    int xrow  = tid >> 1;
    int xhalf = tid & 1;
    int t_x   = g_sorted[p0 + xrow];
    uint32_t xsz = (t_x >= 0) ? 16u : 0u;
    const char* xsrc = (const char*)(nodes + (size_t)(t_x >= 0 ? t_x : 0) * Fd) + xhalf*64;
    // W: 8 threads per k-row, 4x16B each (512B per k-row per stage)
    int wkr = tid >> 3;
    int wj  = tid & 7;
    const char* wsrc = (const char*)Wsrc + (size_t)wkr*Md*4 + wj*64;

    uint32_t xdst = s2u(sm) + (uint32_t)xrow*XPITCH*4 + xhalf*64;
    uint32_t wdst = s2u(sm) + (uint32_t)(TT*XPITCH)*4 + (uint32_t)wkr*WPITCH*4 + wj*64;

    auto load_stage = [&](int s, int b) {
        uint32_t xo = xdst + b*SF*4;
        const char* xs = xsrc + (size_t)s*KC*4;
        #pragma unroll
        for (int i = 0; i < 4; i++) cpa16z(xo + i*16, xs + i*16, xsz);
        uint32_t wo = wdst + b*SF*4;
        const char* ws = wsrc + (size_t)s*KC*Md*4;
        #pragma unroll
        for (int i = 0; i < 4; i++) cpa16(wo + i*16, ws + i*16);
        asm volatile("cp.async.commit_group;" ::: "memory");
    };

    int wid = tid >> 5;
    int lane = tid & 31;
    int g = lane >> 2, tig = lane & 3;
    int warpM = wid & 3, warpN = wid >> 2;   // 4 x 2 warp grid

    float c[2][8][4];
    #pragma unroll
    for (int mt = 0; mt < 2; mt++)
        #pragma unroll
        for (int nt = 0; nt < 8; nt++)
            #pragma unroll
            for (int r = 0; r < 4; r++) c[mt][nt][r] = 0.f;

    load_stage(0, 0);

    for (int s = 0; s < KSTEPS; s++) {
        int b = s & 1;
        if (s + 1 < KSTEPS) load_stage(s + 1, b ^ 1);
        if (s + 1 < KSTEPS) asm volatile("cp.async.wait_group 1;" ::: "memory");
        else                asm volatile("cp.async.wait_group 0;" ::: "memory");
        __syncthreads();

        const float* Xs = sm + b*SF;
        const float* Ws = sm + b*SF + TT*XPITCH;

        #pragma unroll
        for (int kk = 0; kk < 4; kk++) {
            uint32_t a[2][4];
            const float* wb0 = Ws + (kk*8 + tig)*WPITCH;
            #pragma unroll
            for (int mt = 0; mt < 2; mt++) {
                const float* p = wb0 + warpM*32 + mt*16 + g;
                a[mt][0] = f2tf(p[0]);
                a[mt][1] = f2tf(p[8]);
                a[mt][2] = f2tf(p[4*WPITCH]);
                a[mt][3] = f2tf(p[8 + 4*WPITCH]);
            }
            uint32_t bb[8][2];
            #pragma unroll
            for (int nt = 0; nt < 8; nt++) {
                const float* p = Xs + (warpN*64 + nt*8 + g)*XPITCH + kk*8 + tig;
                bb[nt][0] = f2tf(p[0]);
                bb[nt][1] = f2tf(p[4]);
            }
            #pragma unroll
            for (int mt = 0; mt < 2; mt++)
                #pragma unroll
                for (int nt = 0; nt < 8; nt++) {
                    asm volatile(
                        "mma.sync.aligned.m16n8k8.row.col.f32.tf32.tf32.f32 "
                        "{%0,%1,%2,%3}, {%4,%5,%6,%7}, {%8,%9}, {%0,%1,%2,%3};"
                        : "+f"(c[mt][nt][0]), "+f"(c[mt][nt][1]),
                          "+f"(c[mt][nt][2]), "+f"(c[mt][nt][3])
                        : "r"(a[mt][0]), "r"(a[mt][1]), "r"(a[mt][2]), "r"(a[mt][3]),
                          "r"(bb[nt][0]), "r"(bb[nt][1]));
                }
        }
        __syncthreads();
    }

    // epilogue: bias + relu, stage through smem [token][EPITCH], coalesced store
    float* ep = sm;
    #pragma unroll
    for (int mt = 0; mt < 2; mt++) {
        int m = warpM*32 + mt*16 + g;
        float bz0 = sbias[m], bz1 = sbias[m + 8];
        #pragma unroll
        for (int nt = 0; nt < 8; nt++) {
            int n = warpN*64 + nt*8 + 2*tig;
            ep[(size_t)n*EPITCH + m]           = fmaxf(c[mt][nt][0] + bz0, 0.f);
            ep[(size_t)(n+1)*EPITCH + m]       = fmaxf(c[mt][nt][1] + bz0, 0.f);
            ep[(size_t)n*EPITCH + m + 8]       = fmaxf(c[mt][nt][2] + bz1, 0.f);
            ep[(size_t)(n+1)*EPITCH + m + 8]   = fmaxf(c[mt][nt][3] + bz1, 0.f);
        }
    }
    __syncthreads();

    {
        // each thread copies 64 contiguous floats (16 x float4)
        int row = tid >> 1, h2 = tid & 1;
        const float* srow = ep + (size_t)row*EPITCH + h2*64;
        float* drow = dst + (size_t)(p0 + row)*Md + half*128 + h2*64;
        #pragma unroll
        for (int i = 0; i < 16; i++)
            *reinterpret_cast<float4*>(drow + i*4) =
                *reinterpret_cast<const float4*>(srow + i*4);
    }
}

// ---------------- tail: layers 2-4 + rot2 + masked write ----------------
__global__ void __launch_bounds__(256, 2)
k_tail(const float* __restrict__ W2, const float* __restrict__ b2,
       const float* __restrict__ W3, const float* __restrict__ b3,
       const float* __restrict__ W4, const float* __restrict__ b4,
       const float* __restrict__ R2, const float* __restrict__ rb2,
       const int* __restrict__ lengths, float* __restrict__ out)
{
    extern __shared__ float sms[];
    float* sW2  = sms;
    float* sW3  = sW2 + Md*64;
    float* sW4  = sW3 + 64*32;
    float* sR2  = sW4 + 32*14;
    float* sb2  = sR2 + Md*3;
    float* sb3  = sb2 + 64;
    float* sb4  = sb3 + 32;
    float* srb2 = sb4 + 14;
    float* sh1  = srb2 + 3;
    float* sr1  = sh1 + 8*Md;
    float* sh2  = sr1 + 8*Md;
    float* sh3  = sh2 + 8*64;

    __shared__ int soff[Ee+1];
    int tid = threadIdx.x;
    if (tid < Ee+1) soff[tid] = g_off[tid];
    __syncthreads();

    int p0 = blockIdx.x * TT;
    if (p0 >= soff[Ee]) return;
    int e = 0;
    while (e < Ee-1 && p0 >= soff[e+1]) e++;

    const float* gW2 = W2 + (size_t)e*Md*64;
    for (int i = tid; i < Md*64; i += 256) sW2[i] = gW2[i];
    const float* gW3 = W3 + e*64*32;
    for (int i = tid; i < 64*32; i += 256) sW3[i] = gW3[i];
    const float* gW4 = W4 + e*32*14;
    for (int i = tid; i < 32*14; i += 256) sW4[i] = gW4[i];
    const float* gR2 = R2 + e*Md*3;
    for (int i = tid; i < Md*3; i += 256) sR2[i] = gR2[i];
    if (tid < 64) sb2[tid]  = b2[e*64 + tid];
    if (tid < 32) sb3[tid]  = b3[e*32 + tid];
    if (tid < 14) sb4[tid]  = b4[e*14 + tid];
    if (tid < 3)  srb2[tid] = rb2[e*3 + tid];
    __syncthreads();

    int w = tid >> 5, lane = tid & 31;
    float* h1w = sh1 + w*Md;
    float* r1w = sr1 + w*Md;
    float* h2w = sh2 + w*64;
    float* h3w = sh3 + w*32;

    for (int it = 0; it < 16; it++) {
        int p = p0 + w*16 + it;
        int t = g_sorted[p];
        if (t < 0) continue;

        #pragma unroll
        for (int u = 0; u < 8; u++) {
            h1w[lane + 32*u] = g_h1[(size_t)p*Md + lane + 32*u];
            r1w[lane + 32*u] = g_r1[(size_t)p*Md + lane + 32*u];
        }
        __syncwarp();

        int j0 = 2*lane;
        float a0 = sb2[j0], a1 = sb2[j0+1];
        #pragma unroll 4
        for (int m = 0; m < Md; m++) {
            float hv = h1w[m];
            float2 wv = *reinterpret_cast<const float2*>(&sW2[m*64 + j0]);
            a0 += hv * wv.x; a1 += hv * wv.y;
        }
        h2w[j0]   = fmaxf(a0, 0.f);
        h2w[j0+1] = fmaxf(a1, 0.f);
        __syncwarp();

        float a = sb3[lane];
        #pragma unroll
        for (int h = 0; h < 64; h++) a += h2w[h] * sW3[h*32 + lane];
        h3w[lane] = fmaxf(a, 0.f);
        __syncwarp();

        float y = 0.f;
        if (lane < 14) {
            y = sb4[lane];
            #pragma unroll
            for (int gg = 0; gg < 32; gg++) y += h3w[gg] * sW4[gg*14 + lane];
        }

        float r0 = 0.f, r1v = 0.f, r2 = 0.f;
        #pragma unroll
        for (int u = 0; u < 8; u++) {
            int m = lane + 32*u;
            float rv = r1w[m];
            r0  += rv * sR2[m*3 + 0];
            r1v += rv * sR2[m*3 + 1];
            r2  += rv * sR2[m*3 + 2];
        }
        #pragma unroll
        for (int s = 16; s > 0; s >>= 1) {
            r0  += __shfl_xor_sync(0xffffffff, r0, s);
            r1v += __shfl_xor_sync(0xffffffff, r1v, s);
            r2  += __shfl_xor_sync(0xffffffff, r2, s);
        }

        int b = t >> 9, n = t & (Nn - 1);
        bool masked = (n >= lengths[b]);
        float* op = out + (size_t)t*OUTD;
        if (masked) {
            if (lane < OUTD) op[lane] = EPSV;
        } else {
            if (lane < 14) op[lane] = y;
            if (lane == 0) {
                op[14] = r0  + srb2[0];
                op[15] = r1v + srb2[1];
                op[16] = r2  + srb2[2];
            }
        }
    }
}

static const int TAIL_SMEM_BYTES =
    (Md*64 + 64*32 + 32*14 + Md*3 + 64 + 32 + 14 + 3 + 8*Md + 8*Md + 8*64 + 8*32) * 4;

extern "C" void kernel_launch(void* const* d_in, const int* in_sizes, int n_in,
                              void* d_out, int out_size) {
    const float* nodes   = (const float*)d_in[0];
    const int*   sem     = (const int*)  d_in[1];
    const int*   lengths = (const int*)  d_in[2];
    const float* W1 = (const float*)d_in[3];  const float* b1  = (const float*)d_in[4];
    const float* W2 = (const float*)d_in[5];  const float* b2  = (const float*)d_in[6];
    const float* W3 = (const float*)d_in[7];  const float* b3  = (const float*)d_in[8];
    const float* W4 = (const float*)d_in[9];  const float* b4  = (const float*)d_in[10];
    const float* R1 = (const float*)d_in[11]; const float* rb1 = (const float*)d_in[12];
    const float* R2 = (const float*)d_in[13]; const float* rb2 = (const float*)d_in[14];
    float* out = (float*)d_out;

    cudaFuncSetAttribute(k_tail, cudaFuncAttributeMaxDynamicSharedMemorySize, TAIL_SMEM_BYTES);
    cudaFuncSetAttribute(k_gemm1_mma, cudaFuncAttributeMaxDynamicSharedMemorySize, GEMM_SMEM);

    k_init   <<<(SORT_SZ + 255)/256, 256>>>();
    k_count  <<<Tt/256, 256>>>(sem);
    k_offsets<<<1, 32>>>();
    k_scatter<<<Tt/256, 256>>>(sem);
    {
        dim3 g1(NTILES, 4);
        k_gemm1_mma<<<g1, 256, GEMM_SMEM>>>(nodes, W1, b1, R1, rb1);
    }
    k_tail   <<<NTILES, 256, TAIL_SMEM_BYTES>>>(W2, b2, W3, b3, W4, b4, R2, rb2, lengths, out);
}